// round 2
// baseline (speedup 1.0000x reference)
#include <cuda_runtime.h>
#include <cuda_bf16.h>

// Problem shape (fixed by setup_inputs)
#define BB 16
#define NN 2048
#define CC 256
#define KK 16
#define OUTC (3 + CC)   // 259

// Scratch (no cudaMalloc allowed): transposed features + knn indices
__device__ float g_featsT[(size_t)BB * NN * CC];   // (B, N, C)  ~32 MB
__device__ int   g_knn[(size_t)BB * NN * KK];      //  2 MB

// ---------------------------------------------------------------------------
// Kernel 1: transpose features (B, C, N) -> (B, N, C) with 32x32 smem tiles
// ---------------------------------------------------------------------------
__global__ void transpose_kernel(const float* __restrict__ f) {
    __shared__ float tile[32][33];
    const int b  = blockIdx.z;
    const int n0 = blockIdx.x * 32;
    const int c0 = blockIdx.y * 32;
    const int tx = threadIdx.x;   // 32
    const int ty = threadIdx.y;   // 8

    const float* src = f + (size_t)b * CC * NN;
#pragma unroll
    for (int i = 0; i < 32; i += 8)
        tile[ty + i][tx] = src[(size_t)(c0 + ty + i) * NN + n0 + tx];
    __syncthreads();

    float* dst = g_featsT + (size_t)b * NN * CC;
#pragma unroll
    for (int i = 0; i < 32; i += 8)
        dst[(size_t)(n0 + ty + i) * CC + c0 + tx] = tile[tx][ty + i];
}

// ---------------------------------------------------------------------------
// Kernel 2: brute-force kNN (top-16, excluding self) + delta_xyz mean output.
// One block = 128 query points of one batch; all 2048 batch points in smem.
// ---------------------------------------------------------------------------
__global__ void __launch_bounds__(128) knn_kernel(const float* __restrict__ xyz,
                                                  float* __restrict__ out) {
    __shared__ float4 pts[NN];        // 32 KB, padded for LDS.128 broadcast
    __shared__ float  staging[3 * NN];

    const int tilesPerBatch = NN / 128;          // 16
    const int b    = blockIdx.x / tilesPerBatch;
    const int tile = blockIdx.x % tilesPerBatch;

    // Stage 1: fully coalesced flat load of this batch's xyz (6144 floats)
    const float* bx = xyz + (size_t)b * NN * 3;
    for (int i = threadIdx.x; i < 3 * NN; i += 128)
        staging[i] = bx[i];
    __syncthreads();
    // Stage 2: repack to padded float4 (bank-conflict-light: stride 3 reads)
    for (int i = threadIdx.x; i < NN; i += 128)
        pts[i] = make_float4(staging[3 * i], staging[3 * i + 1],
                             staging[3 * i + 2], 0.0f);
    __syncthreads();

    const int n = tile * 128 + threadIdx.x;      // batch-local query index
    const float4 q = pts[n];

    float bestd[KK];
    int   besti[KK];
#pragma unroll
    for (int j = 0; j < KK; ++j) { bestd[j] = 3.4e38f; besti[j] = 0; }
    float worst = 3.4e38f;

#pragma unroll 4
    for (int m = 0; m < NN; ++m) {
        const float4 p = pts[m];
        const float dx = p.x - q.x;
        const float dy = p.y - q.y;
        const float dz = p.z - q.z;
        const float d2 = fmaf(dx, dx, fmaf(dy, dy, dz * dz));
        if (d2 < worst && m != n) {
            // register-resident swap-insert (stable: strict <, ascending m)
            float dd = d2; int ii = m;
#pragma unroll
            for (int j = 0; j < KK; ++j) {
                if (dd < bestd[j]) {
                    const float td = bestd[j]; const int ti = besti[j];
                    bestd[j] = dd; besti[j] = ii;
                    dd = td; ii = ti;
                }
            }
            worst = bestd[KK - 1];
        }
    }

    // Emit knn indices + delta_xyz mean
    float sx = 0.f, sy = 0.f, sz = 0.f;
    const size_t base = ((size_t)b * NN + n) * KK;
#pragma unroll
    for (int j = 0; j < KK; ++j) {
        const int id = besti[j];
        g_knn[base + j] = id;
        const float4 p = pts[id];
        sx += p.x - q.x;
        sy += p.y - q.y;
        sz += p.z - q.z;
    }
    const float inv = 1.0f / (float)KK;
    float* o = out + ((size_t)b * NN + n) * OUTC;
    o[0] = sx * inv;
    o[1] = sy * inv;
    o[2] = sz * inv;
}

// ---------------------------------------------------------------------------
// Kernel 3: feature gather + mean. 256 threads handle 4 query points;
// each point served by 64 threads (4 floats each via float4 loads).
// ---------------------------------------------------------------------------
__global__ void __launch_bounds__(256) gather_kernel(float* __restrict__ out) {
    const int t      = threadIdx.x;
    const int sub    = t >> 6;          // 0..3  (point within block)
    const int lane64 = t & 63;          // 0..63 (float4 slot: covers 256 floats)

    const int bn = blockIdx.x * 4 + sub;        // 0 .. B*N-1
    const int b  = bn >> 11;                    // /2048
    const int n  = bn & (NN - 1);

    __shared__ int sidx[4][KK];
    if (lane64 < KK)
        sidx[sub][lane64] = g_knn[(size_t)bn * KK + lane64];
    __syncthreads();

    const float4* ft = (const float4*)(g_featsT + (size_t)b * NN * CC);
    const int rowQ = CC / 4;   // 64 float4 per row

    float4 acc = make_float4(0.f, 0.f, 0.f, 0.f);
#pragma unroll
    for (int j = 0; j < KK; ++j) {
        const float4 v = ft[(size_t)sidx[sub][j] * rowQ + lane64];
        acc.x += v.x; acc.y += v.y; acc.z += v.z; acc.w += v.w;
    }
    const float4 own = ft[(size_t)n * rowQ + lane64];
    const float inv = 1.0f / (float)KK;

    float* o = out + (size_t)bn * OUTC + 3 + lane64 * 4;
    o[0] = acc.x * inv - own.x;
    o[1] = acc.y * inv - own.y;
    o[2] = acc.z * inv - own.z;
    o[3] = acc.w * inv - own.w;
}

// ---------------------------------------------------------------------------
extern "C" void kernel_launch(void* const* d_in, const int* in_sizes, int n_in,
                              void* d_out, int out_size) {
    const float* xyz      = (const float*)d_in[0];  // (B, N, 3)
    const float* features = (const float*)d_in[1];  // (B, C, N)
    float* out = (float*)d_out;                     // (B, N, 3+C)

    // 1) transpose features -> (B, N, C)
    {
        dim3 grid(NN / 32, CC / 32, BB);
        dim3 block(32, 8);
        transpose_kernel<<<grid, block>>>(features);
    }
    // 2) kNN + delta_xyz
    {
        dim3 grid(BB * (NN / 128));
        knn_kernel<<<grid, 128>>>(xyz, out);
    }
    // 3) feature gather + mean delta
    {
        dim3 grid((BB * NN) / 4);
        gather_kernel<<<grid, 256>>>(out);
    }
}

// round 8
// speedup vs baseline: 1.2800x; 1.2800x over previous
#include <cuda_runtime.h>
#include <cuda_bf16.h>

// Problem shape (fixed by setup_inputs)
#define BB 16
#define NN 2048
#define CC 256
#define KK 16
#define OUTC (3 + CC)   // 259

// knn tuning
#define WARM 64     // candidates handled by direct insertion (seeds `worst`)
#define CS   64     // chunk size between drains
#define CAP  24     // per-thread buffer capacity (overflow -> direct insert)

// Scratch (no cudaMalloc allowed): transposed features + knn indices
__device__ float g_featsT[(size_t)BB * NN * CC];   // (B, N, C)  ~32 MB
__device__ int   g_knn[(size_t)BB * NN * KK];      //  2 MB

// ---------------------------------------------------------------------------
// Kernel 1: transpose features (B, C, N) -> (B, N, C) with 32x32 smem tiles
// ---------------------------------------------------------------------------
__global__ void transpose_kernel(const float* __restrict__ f) {
    __shared__ float tile[32][33];
    const int b  = blockIdx.z;
    const int n0 = blockIdx.x * 32;
    const int c0 = blockIdx.y * 32;
    const int tx = threadIdx.x;   // 32
    const int ty = threadIdx.y;   // 8

    const float* src = f + (size_t)b * CC * NN;
#pragma unroll
    for (int i = 0; i < 32; i += 8)
        tile[ty + i][tx] = src[(size_t)(c0 + ty + i) * NN + n0 + tx];
    __syncthreads();

    float* dst = g_featsT + (size_t)b * NN * CC;
#pragma unroll
    for (int i = 0; i < 32; i += 8)
        dst[(size_t)(n0 + ty + i) * CC + c0 + tx] = tile[tx][ty + i];
}

// ---------------------------------------------------------------------------
// Sorted insert into register-resident top-K (strict <, stable wrt order of
// insertion: earlier-inserted / lower-index wins ties -> matches jax top_k).
// ---------------------------------------------------------------------------
__device__ __forceinline__ void chain_insert(float (&bestd)[KK], int (&besti)[KK],
                                             float d2, int m) {
    float dd = d2; int ii = m;
#pragma unroll
    for (int j = 0; j < KK; ++j) {
        if (dd < bestd[j]) {
            const float td = bestd[j]; const int ti = besti[j];
            bestd[j] = dd; besti[j] = ii;
            dd = td; ii = ti;
        }
    }
}

// ---------------------------------------------------------------------------
// Kernel 2: brute-force kNN (top-16, excluding self) + delta_xyz mean output.
// One block = 128 query points of one batch; all 2048 batch points in smem.
// Candidate buffering: the hot scan only does 3 FFMA + threshold test; passing
// candidates are buffered (2B index in smem) and the expensive sorted-insert
// chain runs compacted in per-chunk drains.
// ---------------------------------------------------------------------------
__global__ void __launch_bounds__(128) knn_kernel(const float* __restrict__ xyz,
                                                  float* __restrict__ out) {
    __shared__ float4 pts[NN];                   // 32 KB: (x, y, z, |p|^2)
    __shared__ unsigned short sbuf[CAP][128];    //  6 KB: per-thread columns

    const int tilesPerBatch = NN / 128;          // 16
    const int b    = blockIdx.x / tilesPerBatch;
    const int tile = blockIdx.x % tilesPerBatch;
    const int tid  = threadIdx.x;

    // Load batch points, precompute squared norms
    const float* bx = xyz + (size_t)b * NN * 3;
    for (int i = tid; i < NN; i += 128) {
        const float x = bx[3 * i], y = bx[3 * i + 1], z = bx[3 * i + 2];
        pts[i] = make_float4(x, y, z, fmaf(x, x, fmaf(y, y, z * z)));
    }
    __syncthreads();

    const int n = tile * 128 + tid;              // batch-local query index
    const float4 q = pts[n];
    const float q2x = -2.0f * q.x;
    const float q2y = -2.0f * q.y;
    const float q2z = -2.0f * q.z;
    // d2' = |p|^2 - 2 p.q  (= d2 - |q|^2 : same ordering, 3 FFMA)

    float bestd[KK];
    int   besti[KK];
#pragma unroll
    for (int j = 0; j < KK; ++j) { bestd[j] = 3.4e38f; besti[j] = 0; }
    float worst = 3.4e38f;

    // ---- warm phase: direct insertion to seed `worst` ----
    for (int m = 0; m < WARM; ++m) {
        const float4 p = pts[m];
        const float d2 = fmaf(p.x, q2x, fmaf(p.y, q2y, fmaf(p.z, q2z, p.w)));
        if (d2 < worst && m != n) {
            chain_insert(bestd, besti, d2, m);
            worst = bestd[KK - 1];
        }
    }

    // ---- main phase: buffered scan + per-chunk drains ----
    for (int c0 = WARM; c0 < NN; c0 += CS) {
        int cnt = 0;
#pragma unroll 4
        for (int m = c0; m < c0 + CS; ++m) {
            const float4 p = pts[m];
            const float d2 = fmaf(p.x, q2x, fmaf(p.y, q2y, fmaf(p.z, q2z, p.w)));
            if (d2 < worst && m != n) {
                if (cnt < CAP) {
                    sbuf[cnt][tid] = (unsigned short)m;
                    ++cnt;
                } else {
                    // overflow fallback: correct for any input
                    chain_insert(bestd, besti, d2, m);
                    worst = bestd[KK - 1];
                }
            }
        }
        // drain (ascending m order per lane -> stable tie-break preserved)
        for (int t = 0; t < cnt; ++t) {
            const int m = sbuf[t][tid];
            const float4 p = pts[m];
            const float d2 = fmaf(p.x, q2x, fmaf(p.y, q2y, fmaf(p.z, q2z, p.w)));
            if (d2 < worst) {
                chain_insert(bestd, besti, d2, m);
                worst = bestd[KK - 1];
            }
        }
    }

    // Emit knn indices + delta_xyz mean
    float sx = 0.f, sy = 0.f, sz = 0.f;
    const size_t base = ((size_t)b * NN + n) * KK;
#pragma unroll
    for (int j = 0; j < KK; ++j) {
        const int id = besti[j];
        g_knn[base + j] = id;
        const float4 p = pts[id];
        sx += p.x - q.x;
        sy += p.y - q.y;
        sz += p.z - q.z;
    }
    const float inv = 1.0f / (float)KK;
    float* o = out + ((size_t)b * NN + n) * OUTC;
    o[0] = sx * inv;
    o[1] = sy * inv;
    o[2] = sz * inv;
}

// ---------------------------------------------------------------------------
// Kernel 3: feature gather + mean. 256 threads handle 4 query points;
// each point served by 64 threads (4 floats each via float4 loads).
// ---------------------------------------------------------------------------
__global__ void __launch_bounds__(256) gather_kernel(float* __restrict__ out) {
    const int t      = threadIdx.x;
    const int sub    = t >> 6;          // 0..3  (point within block)
    const int lane64 = t & 63;          // 0..63 (float4 slot: covers 256 floats)

    const int bn = blockIdx.x * 4 + sub;        // 0 .. B*N-1
    const int b  = bn >> 11;                    // /2048
    const int n  = bn & (NN - 1);

    __shared__ int sidx[4][KK];
    if (lane64 < KK)
        sidx[sub][lane64] = g_knn[(size_t)bn * KK + lane64];
    __syncthreads();

    const float4* ft = (const float4*)(g_featsT + (size_t)b * NN * CC);
    const int rowQ = CC / 4;   // 64 float4 per row

    float4 acc = make_float4(0.f, 0.f, 0.f, 0.f);
#pragma unroll
    for (int j = 0; j < KK; ++j) {
        const float4 v = ft[(size_t)sidx[sub][j] * rowQ + lane64];
        acc.x += v.x; acc.y += v.y; acc.z += v.z; acc.w += v.w;
    }
    const float4 own = ft[(size_t)n * rowQ + lane64];
    const float inv = 1.0f / (float)KK;

    float* o = out + (size_t)bn * OUTC + 3 + lane64 * 4;
    o[0] = acc.x * inv - own.x;
    o[1] = acc.y * inv - own.y;
    o[2] = acc.z * inv - own.z;
    o[3] = acc.w * inv - own.w;
}

// ---------------------------------------------------------------------------
extern "C" void kernel_launch(void* const* d_in, const int* in_sizes, int n_in,
                              void* d_out, int out_size) {
    const float* xyz      = (const float*)d_in[0];  // (B, N, 3)
    const float* features = (const float*)d_in[1];  // (B, C, N)
    float* out = (float*)d_out;                     // (B, N, 3+C)

    // 1) transpose features -> (B, N, C)
    {
        dim3 grid(NN / 32, CC / 32, BB);
        dim3 block(32, 8);
        transpose_kernel<<<grid, block>>>(features);
    }
    // 2) kNN + delta_xyz
    {
        dim3 grid(BB * (NN / 128));
        knn_kernel<<<grid, 128>>>(xyz, out);
    }
    // 3) feature gather + mean delta
    {
        dim3 grid((BB * NN) / 4);
        gather_kernel<<<grid, 256>>>(out);
    }
}